// round 17
// baseline (speedup 1.0000x reference)
#include <cuda_runtime.h>
#include <cuda_fp16.h>
#include <math.h>
#include <stdint.h>

// ---------------------------------------------------------------------------
// BagAttentionNet forward.
//   All five dense layers on mma.sync fp16 (HMMA) 2-split/3-product
//   near-fp32 emulation. Activations flow as fp16 (hi,lo) plane pairs:
//   layers 2-5 cp.async A planes directly (no in-loop convert). 2 CTAs/SM.
//   dot + softmax/top-k tail: SIMT fp32.
// ---------------------------------------------------------------------------

#define NB 2048
#define CI 64
#define MR (NB * CI)          // 131072
#define TAU_F 0.95f

// ---------------- scratch (__device__ globals; no allocs allowed) ----------
__device__ __half g_h1p[2ULL * MR * 256];   // h1 planes [2][M][256]
__device__ __half g_h2p[2ULL * MR * 256];   // h2 planes [2][M][256]
__device__ __half g_h3p[2ULL * MR * 128];   // h3 planes [2][M][128]
__device__ __half g_d1p[2ULL * MR * 128];   // d1 planes [2][M][128]
__device__ float g_h3 [(size_t)MR * 128];   // h3 fp32 (for final_kernel)
__device__ float g_d2 [(size_t)MR * 64];
__device__ float g_dd [MR];
__device__ __half g_w1t [2 * 512 * 256];    // W1^T planes [2][256][512]
__device__ __half g_w2t [2 * 256 * 256];
__device__ __half g_w3t [2 * 256 * 128];
__device__ __half g_dw1t[2 * 128 * 128];
__device__ __half g_dw2t[2 * 128 * 64];

// ---------------- helpers ----------------------------------------------------
__device__ __forceinline__ void cp_async16(void* s, const void* g) {
    unsigned sa = (unsigned)__cvta_generic_to_shared(s);
    asm volatile("cp.async.cg.shared.global [%0], [%1], 16;" :: "r"(sa), "l"(g));
}
#define CP_COMMIT() asm volatile("cp.async.commit_group;")

__device__ __forceinline__ void split2(float v, __half& h, __half& m) {
    h = __float2half(v);
    m = __float2half(v - __half2float(h));
}

__device__ __forceinline__ void ldsm_x4(uint32_t& r0, uint32_t& r1,
                                        uint32_t& r2, uint32_t& r3, uint32_t addr) {
    asm volatile("ldmatrix.sync.aligned.m8n8.x4.shared.b16 {%0,%1,%2,%3},[%4];"
        : "=r"(r0), "=r"(r1), "=r"(r2), "=r"(r3) : "r"(addr));
}

__device__ __forceinline__ void hmma16816(float* c, const uint32_t* a, const uint32_t* b) {
    asm volatile("mma.sync.aligned.m16n8k16.row.col.f32.f16.f16.f32 "
        "{%0,%1,%2,%3},{%4,%5,%6,%7},{%8,%9},{%0,%1,%2,%3};"
        : "+f"(c[0]), "+f"(c[1]), "+f"(c[2]), "+f"(c[3])
        : "r"(a[0]), "r"(a[1]), "r"(a[2]), "r"(a[3]), "r"(b[0]), "r"(b[1]));
}

__device__ __forceinline__ float act_apply(float v, int ACT) {
    if (ACT == 1) return v > 0.f ? v : 0.f;
    return __fdividef(1.f, 1.f + __expf(-v));   // ACT==2 fast sigmoid
}

// W[K][N] -> planes [2][N][K] (transpose + 2-split fp16)
__global__ void split_wt_kernel(const float* __restrict__ W,
                                __half* __restrict__ o, int K, int N) {
    int idx = blockIdx.x * blockDim.x + threadIdx.x;
    if (idx >= K * N) return;
    int k = idx / N, n = idx % N;
    __half h, m;
    split2(W[idx], h, m);
    size_t pl = (size_t)K * N;
    size_t off = (size_t)n * K + k;
    o[off] = h; o[pl + off] = m;
}

// ---------------- HMMA 2-split GEMM (2 CTAs/SM) ------------------------------
// INMODE 0: A fp32 [M][K], LDG->split2->STS.  INMODE 1: A planes [2][M][K] fp16,
//   cp.async directly (no convert).
// OUTMODE 0: fp32 out.  OUTMODE 1: fp16 plane-pair out [2][M][ldN].
// OUTMODE 2: planes out (Cout) + fp32 out (Cout2).
// Products hh, hm, mh (mm dropped ~2^-24). CTA tile 128 x BN.
#define TROW 80                            // 64B data + 16B pad
#define TILE_A_B (128 * TROW)              // 10240 per A plane
#define APL_B (2 * TILE_A_B)               // 20480

template<int BN, int ACT, int INMODE, int OUTMODE>
__global__ void __launch_bounds__(256, 2)
hmma_gemm(const void* __restrict__ Ain, const __half* __restrict__ Bp,
          const float* __restrict__ bias, void* __restrict__ Cout,
          float* __restrict__ Cout2, int K, int ldN)
{
    constexpr int TILE_BB = BN * TROW;
    constexpr int BPL = 2 * TILE_BB;
    constexpr int BUF = APL_B + BPL;
    constexpr int NF = BN / 32;                // n-fragments per warp
    constexpr int NB_IT = BN / 32;             // B 16B-chunks per thread

    extern __shared__ char smem[];
    __shared__ float sbias[BN];
    const uint32_t sb = (uint32_t)__cvta_generic_to_shared(smem);
    const int tid = threadIdx.x, wid = tid >> 5, lane = tid & 31;
    const int brow = blockIdx.y * 128, bcol = blockIdx.x * BN;
    const int mbase = (wid >> 2) * 64;
    const int nbase = (wid & 3) * (BN / 4);
    const size_t bplane = (size_t)ldN * K;
    const size_t aplane = (size_t)MR * K;      // INMODE 1 plane stride (elems)
    const int NT = K / 32;

    if (tid < BN) sbias[tid] = bias[bcol + tid];

    const char* Bg = (const char*)Bp;
    const char* Ag = (const char*)Ain;

    auto cp_b = [&](int kt, int b) {
        char* st = smem + b * BUF;
#pragma unroll
        for (int i = 0; i < NB_IT; i++) {
            int c = tid + i * 256;
            int p = c / (BN * 4), rem = c % (BN * 4);
            int row = rem >> 2, col4 = rem & 3;
            cp_async16(st + APL_B + p * TILE_BB + row * TROW + col4 * 16,
                Bg + ((size_t)p * bplane + (size_t)(bcol + row) * K) * 2
                   + (size_t)kt * 64 + col4 * 16);
        }
    };

    // INMODE 1: A planes straight to smem
    auto cp_a = [&](int kt, int b) {
        char* st = smem + b * BUF;
#pragma unroll
        for (int i = 0; i < 4; i++) {
            int c = tid + i * 256;
            int p = c >> 9, rem = c & 511;      // 512 chunks per plane
            int row = rem >> 2, col4 = rem & 3;
            cp_async16(st + p * TILE_A_B + row * TROW + col4 * 16,
                Ag + ((size_t)p * aplane + (size_t)(brow + row) * K) * 2
                   + (size_t)kt * 64 + col4 * 16);
        }
    };

    // INMODE 0: fp32 A via regs
    const int ar = tid >> 1;
    const int ah = (tid & 1) * 16;
    const float* Aptr = (const float*)Ain + (size_t)(brow + ar) * K + ah;
    float4 areg[4];
    auto ldg_a = [&](int kt) {
#pragma unroll
        for (int q = 0; q < 4; q++)
            areg[q] = *(const float4*)(Aptr + (size_t)kt * 32 + q * 4);
    };
    auto sts_a = [&](int b) {
        char* ap = smem + b * BUF;
        const uint32_t off = (uint32_t)ar * TROW + ah * 2;
        __half2 hv[8], mv[8];
#pragma unroll
        for (int q = 0; q < 4; q++) {
            float vv[4] = {areg[q].x, areg[q].y, areg[q].z, areg[q].w};
            __half h[4], mq[4];
#pragma unroll
            for (int e = 0; e < 4; e++) split2(vv[e], h[e], mq[e]);
            hv[q * 2]     = __halves2half2(h[0], h[1]);
            hv[q * 2 + 1] = __halves2half2(h[2], h[3]);
            mv[q * 2]     = __halves2half2(mq[0], mq[1]);
            mv[q * 2 + 1] = __halves2half2(mq[2], mq[3]);
        }
        *(uint4*)(ap + off)                 = *(uint4*)&hv[0];
        *(uint4*)(ap + off + 16)            = *(uint4*)&hv[4];
        *(uint4*)(ap + TILE_A_B + off)      = *(uint4*)&mv[0];
        *(uint4*)(ap + TILE_A_B + off + 16) = *(uint4*)&mv[4];
    };

    float acc[4][NF][4];
#pragma unroll
    for (int i = 0; i < 4; i++)
#pragma unroll
        for (int j = 0; j < NF; j++)
#pragma unroll
            for (int q = 0; q < 4; q++) acc[i][j][q] = 0.f;

    // ---- prologue ----
    if constexpr (INMODE == 0) {
        ldg_a(0); cp_b(0, 0); CP_COMMIT();
        sts_a(0);
        ldg_a(1); cp_b(1, 1); CP_COMMIT();
        asm volatile("cp.async.wait_group 1;");
    } else {
        cp_a(0, 0); cp_b(0, 0); CP_COMMIT();
        cp_a(1, 1); cp_b(1, 1); CP_COMMIT();
        asm volatile("cp.async.wait_group 1;");
    }

    const int a_r  = (lane & 15);
    const int a_kc = (lane & 16) ? 16 : 0;
    const int b_n  = (lane & 7) + ((lane & 16) ? 8 : 0);
    const int b_kc = (lane & 8) ? 16 : 0;

    for (int kt = 0; kt < NT; kt++) {
        const int b = kt & 1;
        __syncthreads();                 // B1: buf b ready
        const uint32_t stb = sb + b * BUF;
#pragma unroll
        for (int k16 = 0; k16 < 2; k16++) {
            const int kk = k16 * 32;
            uint32_t afr[4][4], bfr[NF][2];
#pragma unroll
            for (int pa = 0; pa < 2; pa++) {
                const uint32_t abase = stb + pa * TILE_A_B + kk + a_kc;
#pragma unroll
                for (int mf = 0; mf < 4; mf++)
                    ldsm_x4(afr[mf][0], afr[mf][1], afr[mf][2], afr[mf][3],
                            abase + (mbase + mf * 16 + a_r) * TROW);
                const int npb = 2 - pa;      // hh,hm then mh
#pragma unroll
                for (int pb = 0; pb < 2; pb++) {
                    if (pb >= npb) break;
                    const uint32_t bbase = stb + APL_B + pb * TILE_BB + kk + b_kc;
#pragma unroll
                    for (int nf2 = 0; nf2 < NF / 2; nf2++) {
                        uint32_t r0, r1, r2, r3;
                        ldsm_x4(r0, r1, r2, r3,
                                bbase + (nbase + nf2 * 16 + b_n) * TROW);
                        bfr[nf2 * 2 + 0][0] = r0; bfr[nf2 * 2 + 0][1] = r1;
                        bfr[nf2 * 2 + 1][0] = r2; bfr[nf2 * 2 + 1][1] = r3;
                    }
#pragma unroll
                    for (int mf = 0; mf < 4; mf++)
#pragma unroll
                        for (int nf = 0; nf < NF; nf++)
                            hmma16816(acc[mf][nf], afr[mf], bfr[nf]);
                }
            }
        }
        __syncthreads();                 // B2: buf b free
        if constexpr (INMODE == 0) {
            if (kt + 1 < NT) sts_a(b ^ 1);
            if (kt + 2 < NT) { ldg_a(kt + 2); cp_b(kt + 2, b); CP_COMMIT(); }
        } else {
            if (kt + 2 < NT) { cp_a(kt + 2, b); cp_b(kt + 2, b); CP_COMMIT(); }
        }
        if (kt + 1 < NT) {
            if (kt + 2 < NT) asm volatile("cp.async.wait_group 1;");
            else             asm volatile("cp.async.wait_group 0;");
        }
    }

    // ---- epilogue: bias + act ----
    const int qr = lane >> 2, qc = (lane & 3) * 2;
    const size_t pstrC = (size_t)MR * ldN;
#pragma unroll
    for (int mf = 0; mf < 4; mf++) {
#pragma unroll
        for (int half = 0; half < 2; half++) {
            const int row = brow + mbase + mf * 16 + qr + half * 8;
#pragma unroll
            for (int nf = 0; nf < NF; nf++) {
                const int colL = nbase + nf * 8 + qc;
                float v0 = act_apply(acc[mf][nf][half * 2 + 0] + sbias[colL],     ACT);
                float v1 = act_apply(acc[mf][nf][half * 2 + 1] + sbias[colL + 1], ACT);
                const size_t base = (size_t)row * ldN + bcol + colL;
                if constexpr (OUTMODE == 0) {
                    *(float2*)((float*)Cout + base) = make_float2(v0, v1);
                } else {
                    __half* Cp = (__half*)Cout;
                    __half h0, m0, h1, m1;
                    split2(v0, h0, m0); split2(v1, h1, m1);
                    *(__half2*)(Cp + base)         = __halves2half2(h0, h1);
                    *(__half2*)(Cp + pstrC + base) = __halves2half2(m0, m1);
                    if constexpr (OUTMODE == 2)
                        *(float2*)(Cout2 + base) = make_float2(v0, v1);
                }
            }
        }
    }
}

#define HS128 (2 * (APL_B + 2 * (128 * TROW)))   // 81920
#define HS64  (2 * (APL_B + 2 * ( 64 * TROW)))   // 61440

// d[r] = d2[r,:] . D3 + db3   (K = 64)
__global__ void dot_kernel(const float* __restrict__ d2, const float* __restrict__ D3,
                           const float* __restrict__ db3, float* __restrict__ dd)
{
    int gw   = (blockIdx.x * blockDim.x + threadIdx.x) >> 5;
    int lane = threadIdx.x & 31;
    if (gw >= MR) return;
    const float* row = d2 + (size_t)gw * 64;
    float s = row[lane] * D3[lane] + row[lane + 32] * D3[lane + 32];
#pragma unroll
    for (int o = 16; o > 0; o >>= 1) s += __shfl_down_sync(0xffffffffu, s, o);
    if (lane == 0) dd[gw] = s + db3[0];
}

// Per-bag: gumbel softmax, top-20 keep (stable), re-softmax, aggregate, project.
__global__ void __launch_bounds__(128)
final_kernel(const float* __restrict__ dd, const float* __restrict__ m,
             const float* __restrict__ u, const float* __restrict__ h3,
             const float* __restrict__ E, const float* __restrict__ eb,
             float* __restrict__ out_w, float* __restrict__ out_s)
{
    const int bag = blockIdx.x;
    const int t   = threadIdx.x;

    __shared__ float sm[64];
    __shared__ float wf[64];
    __shared__ float red[128];

    float z = 0.f;
    if (t < 64) {
        float logit = m[bag * 64 + t] * dd[bag * 64 + t];
        float uu = u[bag * 64 + t];
        float g = -logf(-logf(uu));
        z = (logit + g) / TAU_F;
    }

    red[t] = (t < 64) ? z : -INFINITY;
    __syncthreads();
#pragma unroll
    for (int s = 64; s >= 1; s >>= 1) {
        if (t < s) red[t] = fmaxf(red[t], red[t + s]);
        __syncthreads();
    }
    float zmax = red[0];
    __syncthreads();

    float e = (t < 64) ? expf(z - zmax) : 0.f;
    red[t] = e;
    __syncthreads();
#pragma unroll
    for (int s = 64; s >= 1; s >>= 1) {
        if (t < s) red[t] += red[t + s];
        __syncthreads();
    }
    float psum = red[0];
    __syncthreads();

    float p = e / psum;
    if (t < 64) sm[t] = p;
    __syncthreads();

    int keep = 0;
    if (t < 64) {
        int pos = 0;
#pragma unroll 8
        for (int j = 0; j < 64; j++) {
            float o = sm[j];
            pos += (o < p) || (o == p && j < t);
        }
        keep = (pos >= 44);
    }

    red[t] = (t < 64 && keep) ? p : -INFINITY;
    __syncthreads();
#pragma unroll
    for (int s = 64; s >= 1; s >>= 1) {
        if (t < s) red[t] = fmaxf(red[t], red[t + s]);
        __syncthreads();
    }
    float m2 = red[0];
    __syncthreads();

    float e2 = (t < 64 && keep) ? expf(p - m2) : 0.f;
    red[t] = e2;
    __syncthreads();
#pragma unroll
    for (int s = 64; s >= 1; s >>= 1) {
        if (t < s) red[t] += red[t + s];
        __syncthreads();
    }
    float s2 = red[0];
    __syncthreads();

    float wfin = (t < 64 && keep) ? (e2 / s2) : 0.f;
    if (t < 64) {
        wf[t] = wfin;
        out_w[bag * 64 + t] = wfin;
    }
    __syncthreads();

    const float* hb = h3 + (size_t)bag * 64 * 128;
    float agg = 0.f;
#pragma unroll 8
    for (int c = 0; c < 64; c++) agg += wf[c] * hb[c * 128 + t];
    red[t] = agg * E[t];
    __syncthreads();
#pragma unroll
    for (int s = 64; s >= 1; s >>= 1) {
        if (t < s) red[t] += red[t + s];
        __syncthreads();
    }
    if (t == 0) out_s[bag] = red[0] + eb[0];
}

// ---------------- launch ------------------------------------------------------
extern "C" void kernel_launch(void* const* d_in, const int* in_sizes, int n_in,
                              void* d_out, int out_size)
{
    const float* x   = (const float*)d_in[0];
    const float* m   = (const float*)d_in[1];
    const float* u   = (const float*)d_in[2];
    const float* W1  = (const float*)d_in[3];
    const float* b1  = (const float*)d_in[4];
    const float* W2  = (const float*)d_in[5];
    const float* b2  = (const float*)d_in[6];
    const float* W3  = (const float*)d_in[7];
    const float* b3  = (const float*)d_in[8];
    const float* D1  = (const float*)d_in[9];
    const float* db1 = (const float*)d_in[10];
    const float* D2  = (const float*)d_in[11];
    const float* db2 = (const float*)d_in[12];
    const float* D3  = (const float*)d_in[13];
    const float* db3 = (const float*)d_in[14];
    const float* E   = (const float*)d_in[15];
    const float* eb  = (const float*)d_in[16];
    float* out = (float*)d_out;

    __half *w1t, *w2t, *w3t, *dw1t, *dw2t, *h1p, *h2p, *h3p, *d1p;
    float *h3, *d2, *dd;
    cudaGetSymbolAddress((void**)&w1t,  g_w1t);
    cudaGetSymbolAddress((void**)&w2t,  g_w2t);
    cudaGetSymbolAddress((void**)&w3t,  g_w3t);
    cudaGetSymbolAddress((void**)&dw1t, g_dw1t);
    cudaGetSymbolAddress((void**)&dw2t, g_dw2t);
    cudaGetSymbolAddress((void**)&h1p,  g_h1p);
    cudaGetSymbolAddress((void**)&h2p,  g_h2p);
    cudaGetSymbolAddress((void**)&h3p,  g_h3p);
    cudaGetSymbolAddress((void**)&d1p,  g_d1p);
    cudaGetSymbolAddress((void**)&h3,   g_h3);
    cudaGetSymbolAddress((void**)&d2,   g_d2);
    cudaGetSymbolAddress((void**)&dd,   g_dd);

    static int attr_done = 0;
    if (!attr_done) {
        cudaFuncSetAttribute(hmma_gemm<128,1,0,1>, cudaFuncAttributeMaxDynamicSharedMemorySize, HS128);
        cudaFuncSetAttribute(hmma_gemm<128,1,1,1>, cudaFuncAttributeMaxDynamicSharedMemorySize, HS128);
        cudaFuncSetAttribute(hmma_gemm<128,1,1,2>, cudaFuncAttributeMaxDynamicSharedMemorySize, HS128);
        cudaFuncSetAttribute(hmma_gemm<128,2,1,1>, cudaFuncAttributeMaxDynamicSharedMemorySize, HS128);
        cudaFuncSetAttribute(hmma_gemm< 64,2,1,0>, cudaFuncAttributeMaxDynamicSharedMemorySize, HS64);
        attr_done = 1;
    }

    // weight splits (tiny)
    split_wt_kernel<<<(512 * 256 + 255) / 256, 256>>>(W1, w1t, 512, 256);
    split_wt_kernel<<<(256 * 256 + 255) / 256, 256>>>(W2, w2t, 256, 256);
    split_wt_kernel<<<(256 * 128 + 255) / 256, 256>>>(W3, w3t, 256, 128);
    split_wt_kernel<<<(128 * 128 + 255) / 256, 256>>>(D1, dw1t, 128, 128);
    split_wt_kernel<<<(128 *  64 + 255) / 256, 256>>>(D2, dw2t, 128, 64);

    // dense chain on HMMA (fp16 2-split/3-product), fp16 plane activations
    hmma_gemm<128,1,0,1><<<dim3(2, MR / 128), 256, HS128>>>(x,   w1t,  b1,  h1p, nullptr, 512, 256);
    hmma_gemm<128,1,1,1><<<dim3(2, MR / 128), 256, HS128>>>(h1p, w2t,  b2,  h2p, nullptr, 256, 256);
    hmma_gemm<128,1,1,2><<<dim3(1, MR / 128), 256, HS128>>>(h2p, w3t,  b3,  h3p, h3,      256, 128);
    hmma_gemm<128,2,1,1><<<dim3(1, MR / 128), 256, HS128>>>(h3p, dw1t, db1, d1p, nullptr, 128, 128);
    hmma_gemm< 64,2,1,0><<<dim3(1, MR / 128), 256, HS64 >>>(d1p, dw2t, db2, d2,  nullptr, 128, 64);

    // tail
    dot_kernel<<<MR / 8, 256>>>(d2, D3, db3, dd);
    final_kernel<<<NB, 128>>>(dd, m, u, h3, E, eb, out, out + MR);
}